// round 1
// baseline (speedup 1.0000x reference)
#include <cuda_runtime.h>
#include <math.h>

#define HH 128
#define WW 224
#define NN 4
#define HW (HH*WW)   // 28672

// ---------------- scratch (static __device__ globals, per harness rules) ---
__device__ float g_Ar[(size_t)NN*144*HW];
__device__ float g_Ai[(size_t)NN*144*HW];
__device__ float g_Br[(size_t)NN*144*HW];
__device__ float g_Bi[(size_t)NN*144*HW];
__device__ float g_mr[144], g_sr[144], g_mi[144], g_si[144];

// ---------------- fused complex 3x3 conv -----------------------------------
// Output tile: 16(h) x 32(w) per block; 256 threads, each computes 2 adjacent
// w-pixels for COUT_T output channel pairs (real+imag accumulated together).
// CPLX=false: input imaginary part is identically zero (layer 1).
template<int COUT_T, bool CPLX>
__global__ __launch_bounds__(256, 2)
void conv3x3(const float* __restrict__ xr, const float* __restrict__ xi,
             const float* __restrict__ wr, const float* __restrict__ wi,
             float* __restrict__ yr, float* __restrict__ yi,
             int Cin, int Cout)
{
    __shared__ float sxr[18*35];
    __shared__ float sxi[CPLX ? 18*35 : 1];
    __shared__ float swr[COUT_T*9];
    __shared__ float swi[COUT_T*9];

    const int t  = threadIdx.x;
    const int tx = t & 15;        // 0..15 -> w pair
    const int ty = t >> 4;        // 0..15 -> h row
    const int wbase = blockIdx.x * 32;
    const int hbase = blockIdx.y * 16;
    const int groups = Cout / COUT_T;
    const int cog = blockIdx.z % groups;
    const int n   = blockIdx.z / groups;
    const int cobase = cog * COUT_T;

    float accR[COUT_T][2];
    float accI[COUT_T][2];
#pragma unroll
    for (int co = 0; co < COUT_T; ++co) {
        accR[co][0] = accR[co][1] = 0.f;
        accI[co][0] = accI[co][1] = 0.f;
    }

    for (int ci = 0; ci < Cin; ++ci) {
        const float* pr = xr + ((size_t)(n*Cin + ci))*HW;
        const float* pi = CPLX ? (xi + ((size_t)(n*Cin + ci))*HW) : nullptr;

        // cooperative halo-tile load (18 x 34 valid, stride 35 = conflict-free)
        for (int idx = t; idx < 18*34; idx += 256) {
            int r = idx / 34, c = idx - r*34;
            int gh = hbase - 1 + r, gw = wbase - 1 + c;
            bool ok = ((unsigned)gh < HH) && ((unsigned)gw < WW);
            sxr[r*35 + c] = ok ? pr[gh*WW + gw] : 0.f;
            if (CPLX) sxi[r*35 + c] = ok ? pi[gh*WW + gw] : 0.f;
        }
        if (t < COUT_T*9) {
            int co = t / 9, k = t - co*9;
            swr[t] = wr[((size_t)(cobase+co)*Cin + ci)*9 + k];
            swi[t] = wi[((size_t)(cobase+co)*Cin + ci)*9 + k];
        }
        __syncthreads();

        // window registers for the 2-pixel pair
        float ar[3][4], ai[3][4];
#pragma unroll
        for (int r = 0; r < 3; ++r)
#pragma unroll
            for (int c = 0; c < 4; ++c) {
                ar[r][c] = sxr[(ty+r)*35 + 2*tx + c];
                if (CPLX) ai[r][c] = sxi[(ty+r)*35 + 2*tx + c];
            }

#pragma unroll
        for (int co = 0; co < COUT_T; ++co) {
#pragma unroll
            for (int kh = 0; kh < 3; ++kh)
#pragma unroll
                for (int kw = 0; kw < 3; ++kw) {
                    float wrv = swr[co*9 + kh*3 + kw];
                    float wiv = swi[co*9 + kh*3 + kw];
#pragma unroll
                    for (int p = 0; p < 2; ++p) {
                        float a = ar[kh][kw+p];
                        accR[co][p] = fmaf(a, wrv, accR[co][p]);
                        accI[co][p] = fmaf(a, wiv, accI[co][p]);
                        if (CPLX) {
                            float b = ai[kh][kw+p];
                            accR[co][p] = fmaf(b, -wiv, accR[co][p]);
                            accI[co][p] = fmaf(b,  wrv, accI[co][p]);
                        }
                    }
                }
        }
        __syncthreads();
    }

    const int h = hbase + ty, w0 = wbase + 2*tx;
#pragma unroll
    for (int co = 0; co < COUT_T; ++co) {
        size_t o = ((size_t)(n*Cout + cobase + co))*HW + h*WW + w0;
        yr[o]   = accR[co][0];
        yr[o+1] = accR[co][1];
        yi[o]   = accI[co][0];
        yi[o+1] = accI[co][1];
    }
}

// ---------------- BN stats: one block per channel, deterministic -----------
__global__ void bn_stats(const float* __restrict__ x, int C,
                         float* __restrict__ mean, float* __restrict__ rstd)
{
    const int c = blockIdx.x, t = threadIdx.x;
    double s = 0.0, q = 0.0;
    for (int n = 0; n < NN; ++n) {
        const float* p = x + ((size_t)(n*C + c))*HW;
        for (int i = t; i < HW; i += 256) {
            double v = p[i];
            s += v; q += v*v;
        }
    }
    __shared__ double ss[256], sq[256];
    ss[t] = s; sq[t] = q;
    __syncthreads();
    for (int o = 128; o > 0; o >>= 1) {
        if (t < o) { ss[t] += ss[t+o]; sq[t] += sq[t+o]; }
        __syncthreads();
    }
    if (t == 0) {
        double cnt = (double)NN * HW;
        double m = ss[0] / cnt;
        double v = sq[0] / cnt - m*m;
        mean[c] = (float)m;
        rstd[c] = (float)(1.0 / sqrt(v + 1e-5));
    }
}

// ---------------- BN apply + ReLU (in place) --------------------------------
__global__ void bn_apply_relu(float* __restrict__ x, int C,
                              const float* __restrict__ mean,
                              const float* __restrict__ rstd,
                              const float* __restrict__ g,
                              const float* __restrict__ b)
{
    const int c = blockIdx.y, n = blockIdx.z;
    const float sc = rstd[c] * g[c];
    const float bi = b[c] - mean[c] * sc;
    size_t o = ((size_t)(n*C + c))*HW + (size_t)blockIdx.x*256 + threadIdx.x;
    float v = fmaf(x[o], sc, bi);
    x[o] = fmaxf(v, 0.f);
}

// ---------------- complex magnitude ----------------------------------------
__global__ void magnitude(const float* __restrict__ xr,
                          const float* __restrict__ xi,
                          float* __restrict__ m)
{
    size_t i = (size_t)blockIdx.x*256 + threadIdx.x;
    float a = xr[i], b = xi[i];
    m[i] = sqrtf(a*a + b*b);
}

// ---------------- head: 96 -> 3 channels, bias, sigmoid on ch0 -------------
__global__ __launch_bounds__(256)
void conv_head(const float* __restrict__ m,
               const float* __restrict__ wc, const float* __restrict__ bc,
               const float* __restrict__ wg, const float* __restrict__ bg,
               float* __restrict__ out)
{
    __shared__ float sm[18*35];
    __shared__ float sw[3*9];
    const int t = threadIdx.x;
    const int tx = t & 15, ty = t >> 4;
    const int wbase = blockIdx.x * 32, hbase = blockIdx.y * 16;
    const int n = blockIdx.z;

    float acc[3][2] = {};
    for (int ci = 0; ci < 96; ++ci) {
        const float* p = m + ((size_t)(n*96 + ci))*HW;
        for (int idx = t; idx < 18*34; idx += 256) {
            int r = idx / 34, c = idx - r*34;
            int gh = hbase - 1 + r, gw = wbase - 1 + c;
            sm[r*35 + c] = (((unsigned)gh < HH) && ((unsigned)gw < WW))
                           ? p[gh*WW + gw] : 0.f;
        }
        if (t < 27) {
            int co = t / 9, k = t - co*9;
            sw[t] = (co == 0) ? wc[(size_t)ci*9 + k]
                              : wg[((size_t)(co-1)*96 + ci)*9 + k];
        }
        __syncthreads();
#pragma unroll
        for (int kh = 0; kh < 3; ++kh)
#pragma unroll
            for (int kw = 0; kw < 3; ++kw) {
                float a0 = sm[(ty+kh)*35 + 2*tx + kw];
                float a1 = sm[(ty+kh)*35 + 2*tx + kw + 1];
#pragma unroll
                for (int co = 0; co < 3; ++co) {
                    float wv = sw[co*9 + kh*3 + kw];
                    acc[co][0] = fmaf(a0, wv, acc[co][0]);
                    acc[co][1] = fmaf(a1, wv, acc[co][1]);
                }
            }
        __syncthreads();
    }
    const int h = hbase + ty, w0 = wbase + 2*tx;
    const float b0 = bc[0], b1 = bg[0], b2 = bg[1];
    float c0a = acc[0][0] + b0, c0b = acc[0][1] + b0;
    c0a = 1.f / (1.f + expf(-c0a));
    c0b = 1.f / (1.f + expf(-c0b));
    size_t o0 = ((size_t)(n*3 + 0))*HW + h*WW + w0;
    size_t o1 = ((size_t)(n*3 + 1))*HW + h*WW + w0;
    size_t o2 = ((size_t)(n*3 + 2))*HW + h*WW + w0;
    out[o0] = c0a;            out[o0+1] = c0b;
    out[o1] = acc[1][0] + b1; out[o1+1] = acc[1][1] + b1;
    out[o2] = acc[2][0] + b2; out[o2+1] = acc[2][1] + b2;
}

// ---------------- driver -----------------------------------------------------
extern "C" void kernel_launch(void* const* d_in, const int* in_sizes, int n_in,
                              void* d_out, int out_size)
{
    (void)in_sizes; (void)n_in; (void)out_size;
    const float* x   = (const float*)d_in[0];
    const float* w1r = (const float*)d_in[1];
    const float* w1i = (const float*)d_in[2];
    const float* g1  = (const float*)d_in[3];
    const float* b1  = (const float*)d_in[4];
    const float* w2r = (const float*)d_in[5];
    const float* w2i = (const float*)d_in[6];
    const float* g2  = (const float*)d_in[7];
    const float* b2  = (const float*)d_in[8];
    const float* w3r = (const float*)d_in[9];
    const float* w3i = (const float*)d_in[10];
    const float* g3  = (const float*)d_in[11];
    const float* b3  = (const float*)d_in[12];
    const float* w4r = (const float*)d_in[13];
    const float* w4i = (const float*)d_in[14];
    const float* g4  = (const float*)d_in[15];
    const float* b4  = (const float*)d_in[16];
    const float* wc  = (const float*)d_in[17];
    const float* bc  = (const float*)d_in[18];
    const float* wg  = (const float*)d_in[19];
    const float* bg  = (const float*)d_in[20];
    float* out = (float*)d_out;

    float *Ar, *Ai, *Br, *Bi, *mr, *sr, *mi, *si;
    cudaGetSymbolAddress((void**)&Ar, g_Ar);
    cudaGetSymbolAddress((void**)&Ai, g_Ai);
    cudaGetSymbolAddress((void**)&Br, g_Br);
    cudaGetSymbolAddress((void**)&Bi, g_Bi);
    cudaGetSymbolAddress((void**)&mr, g_mr);
    cudaGetSymbolAddress((void**)&sr, g_sr);
    cudaGetSymbolAddress((void**)&mi, g_mi);
    cudaGetSymbolAddress((void**)&si, g_si);

    const dim3 blk(256);

    // Layer 1: real input -> complex (256 -> 144)
    conv3x3<8, false><<<dim3(7, 8, 4*(144/8)), blk>>>(x, nullptr, w1r, w1i,
                                                      Ar, Ai, 256, 144);
    bn_stats<<<144, 256>>>(Ar, 144, mr, sr);
    bn_stats<<<144, 256>>>(Ai, 144, mi, si);
    bn_apply_relu<<<dim3(112, 144, 4), 256>>>(Ar, 144, mr, sr, g1, b1);
    bn_apply_relu<<<dim3(112, 144, 4), 256>>>(Ai, 144, mi, si, g1, b1);

    // Layer 2: complex (144 -> 96)
    conv3x3<8, true><<<dim3(7, 8, 4*(96/8)), blk>>>(Ar, Ai, w2r, w2i,
                                                    Br, Bi, 144, 96);
    bn_stats<<<96, 256>>>(Br, 96, mr, sr);
    bn_stats<<<96, 256>>>(Bi, 96, mi, si);
    bn_apply_relu<<<dim3(112, 96, 4), 256>>>(Br, 96, mr, sr, g2, b2);
    bn_apply_relu<<<dim3(112, 96, 4), 256>>>(Bi, 96, mi, si, g2, b2);

    // Layer 3: complex (96 -> 96)
    conv3x3<8, true><<<dim3(7, 8, 4*(96/8)), blk>>>(Br, Bi, w3r, w3i,
                                                    Ar, Ai, 96, 96);
    bn_stats<<<96, 256>>>(Ar, 96, mr, sr);
    bn_stats<<<96, 256>>>(Ai, 96, mi, si);
    bn_apply_relu<<<dim3(112, 96, 4), 256>>>(Ar, 96, mr, sr, g3, b3);
    bn_apply_relu<<<dim3(112, 96, 4), 256>>>(Ai, 96, mi, si, g3, b3);

    // Layer 4: complex (96 -> 96)
    conv3x3<8, true><<<dim3(7, 8, 4*(96/8)), blk>>>(Ar, Ai, w4r, w4i,
                                                    Br, Bi, 96, 96);
    bn_stats<<<96, 256>>>(Br, 96, mr, sr);
    bn_stats<<<96, 256>>>(Bi, 96, mi, si);
    bn_apply_relu<<<dim3(112, 96, 4), 256>>>(Br, 96, mr, sr, g4, b4);
    bn_apply_relu<<<dim3(112, 96, 4), 256>>>(Bi, 96, mi, si, g4, b4);

    // |z| then 3-channel head (ch0 sigmoid)
    magnitude<<<(4*96*HW)/256, 256>>>(Br, Bi, Ar);
    conv_head<<<dim3(7, 8, 4), 256>>>(Ar, wc, bc, wg, bg, out);
}